// round 5
// baseline (speedup 1.0000x reference)
#include <cuda_runtime.h>
#include <cuda_bf16.h>
#include <math.h>
#include <stdint.h>

// ---------------- problem constants ----------------
#define BB 4
#define CC 128
#define HIMG 192
#define WIMG 192
#define PP (HIMG*WIMG)          // 36864
#define NH 2
#define HD 64
#define BNH (BB*NH)             // 8
#define NBX 288                 // PP/128 (avln CTAs per image)
#define NBX2 144                // PP/256 (gemm CTAs per image)
#define NDW 36                  // PP/1024 dw blocks per plane
#define NCH2 32                 // gram chunks per (b,head)
#define CPX2 (PP/NCH2)          // 1152 px per gram CTA

#define ELEMS ((size_t)BB*CC*PP)

// ---------------- scratch ----------------
__device__ float g_t [ELEMS];
__device__ float g_t2[ELEMS];
__device__ float g_t3[ELEMS];
__device__ float g_q [ELEMS];
__device__ float g_k [ELEMS];
__device__ float g_v [ELEMS];
__device__ float g_norm_q[BB*CC];
__device__ float g_norm_k[BB*CC];
__device__ float g_part[(size_t)BNH*NCH2*HD*HD];
__device__ float g_a[BNH*HD*HD];
__device__ float g_sqq[BB*CC*NDW];
__device__ float g_sqk[BB*CC*NDW];
__device__ float g_psum[BB*CC*NBX2];
__device__ float g_pmax[BB*CC*NBX2];

__device__ __forceinline__ float gelu_f(float x) {
    return 0.5f * x * (1.0f + erff(x * 0.70710678118654752f));
}

// ================= mma.sync helpers =================
__device__ __forceinline__ uint32_t smem_u32(const void* p) {
    uint32_t a;
    asm("{ .reg .u64 t; cvta.to.shared.u64 t, %1; cvt.u32.u64 %0, t; }" : "=r"(a) : "l"(p));
    return a;
}
__device__ __forceinline__ void ldsm_x4(uint32_t* r, uint32_t addr) {
    asm volatile("ldmatrix.sync.aligned.m8n8.x4.shared.b16 {%0,%1,%2,%3}, [%4];"
        : "=r"(r[0]), "=r"(r[1]), "=r"(r[2]), "=r"(r[3]) : "r"(addr));
}
__device__ __forceinline__ void ldsm_x4_t(uint32_t* r, uint32_t addr) {
    asm volatile("ldmatrix.sync.aligned.m8n8.x4.trans.shared.b16 {%0,%1,%2,%3}, [%4];"
        : "=r"(r[0]), "=r"(r[1]), "=r"(r[2]), "=r"(r[3]) : "r"(addr));
}
__device__ __forceinline__ void mma_bf16(float* c, const uint32_t* a, uint32_t b0, uint32_t b1) {
    asm volatile(
        "mma.sync.aligned.m16n8k16.row.col.f32.bf16.bf16.f32 "
        "{%0,%1,%2,%3}, {%4,%5,%6,%7}, {%8,%9}, {%0,%1,%2,%3};"
        : "+f"(c[0]), "+f"(c[1]), "+f"(c[2]), "+f"(c[3])
        : "r"(a[0]), "r"(a[1]), "r"(a[2]), "r"(a[3]), "r"(b0), "r"(b1));
}
__device__ __forceinline__ void split2(float x, float y, uint32_t& hi, uint32_t& lo) {
    __nv_bfloat16 hx = __float2bfloat16_rn(x);
    __nv_bfloat16 hy = __float2bfloat16_rn(y);
    __nv_bfloat16 lx = __float2bfloat16_rn(x - __bfloat162float(hx));
    __nv_bfloat16 ly = __float2bfloat16_rn(y - __bfloat162float(hy));
    hi = (uint32_t)__bfloat16_as_ushort(hx) | ((uint32_t)__bfloat16_as_ushort(hy) << 16);
    lo = (uint32_t)__bfloat16_as_ushort(lx) | ((uint32_t)__bfloat16_as_ushort(ly) << 16);
}

// ============== 512-thread fused HMMA pointwise GEMM ==============
// Y_s[co,p] = sum_ci W_s[co,ci]*X[ci,p]; co=128, ci=128*KPASS, CTA tile 128 x 256.
// bf16 split products hi*hi + lo*hi + hi*lo, fp32 accumulate.
// LNIN: LayerNorm folded algebraically: W'=W*lnw staged; epilogue applies
//       y = r_px*(acc - mu_px*c2[co]) + c1[co], c1 = W.lnb, c2 = sum W'.
// POOL: epilogue reduces per-channel sum/max into partial buffers (no store).
#define LDW 136
#define LDB 264
#define OX_HI 0
#define OX_LO 67584
#define OW_HI 135168
#define OW_LO 169984
#define OF_EXTRA 204800
#define SM512 (OF_EXTRA + 1792*4)   // 211968

template<int KPASS, int NSET, bool LNIN, bool GIN, bool GOUT, bool POOL, bool STORE>
__global__ void __launch_bounds__(512, 1) gemm512(
    const float* __restrict__ W0, const float* __restrict__ W1, const float* __restrict__ W2,
    const float* __restrict__ X0, const float* __restrict__ X1, long xstride,
    const float* __restrict__ lnw, const float* __restrict__ lnb,
    float* __restrict__ Y0, float* __restrict__ Y1, float* __restrict__ Y2, long ystride,
    float* __restrict__ psum, float* __restrict__ pmax)
{
    extern __shared__ __align__(16) char smem[];
    uint32_t sb = smem_u32(smem);
    uint32_t sX_hi = sb + OX_HI, sX_lo = sb + OX_LO;
    uint32_t sW_hi = sb + OW_HI, sW_lo = sb + OW_LO;
    float* fx   = (float*)(smem + OF_EXTRA);
    float* red  = fx;            // [1024]
    float* muS  = fx + 1024;     // [256]
    float* rsS  = fx + 1280;     // [256]
    float* c1S  = fx + 1536;     // [128]
    float* c2S  = fx + 1664;     // [128]

    const int tid = threadIdx.x;
    const int wid = tid >> 5, lane = tid & 31;
    const int bi = blockIdx.y;
    const int p0 = blockIdx.x * 256;

    const int wm = wid & 1, wn = wid >> 1;       // 2 x 8 warps
    const int m0 = wm * 64, n0 = wn * 32;
    const int ar = (lane & 7) + ((lane >> 3) & 1) * 8;
    const int ac = ((lane >> 4) & 1) * 8;
    const uint32_t offW = (uint32_t)((m0 + ar) * LDW + ac) * 2;
    const uint32_t offX = (uint32_t)(ar * LDB + n0 + ac) * 2;

    float C[4][4][4];
    if (KPASS > 1) {
        #pragma unroll
        for (int mt = 0; mt < 4; mt++)
            #pragma unroll
            for (int nt = 0; nt < 4; nt++)
                #pragma unroll
                for (int e = 0; e < 4; e++) C[mt][nt][e] = 0.f;
    }

    const int WROW = 128 * KPASS;

    #pragma unroll
    for (int pass = 0; pass < KPASS; pass++) {
        if (pass > 0) __syncthreads();
        const float* Xsrc = ((pass == 0) ? X0 : X1) + (long)bi * xstride;

        // ---- stage X tile [128ci][256px] raw split (GIN: gelu first) ----
        #pragma unroll
        for (int it = 0; it < 16; it++) {
            int idx = (it * 512 + tid) * 4;
            int kk = idx >> 8, nn = idx & 255;
            float4 v = *(const float4*)&Xsrc[(long)kk * PP + p0 + nn];
            if (GIN) { v.x = gelu_f(v.x); v.y = gelu_f(v.y); v.z = gelu_f(v.z); v.w = gelu_f(v.w); }
            uint32_t h0, l0, h1, l1;
            split2(v.x, v.y, h0, l0);
            split2(v.z, v.w, h1, l1);
            uint32_t off = (uint32_t)(kk * LDB + nn) * 2;
            asm volatile("st.shared.v2.b32 [%0], {%1,%2};" :: "r"(sX_hi + off), "r"(h0), "r"(h1));
            asm volatile("st.shared.v2.b32 [%0], {%1,%2};" :: "r"(sX_lo + off), "r"(l0), "r"(l1));
        }

        if (LNIN) {
            __syncthreads();
            // per-pixel stats over 128 channels, reconstructed from hi+lo
            int col = tid & 255, half = tid >> 8;
            float s = 0.f, q2 = 0.f;
            const __nv_bfloat16* hb = (const __nv_bfloat16*)(smem + OX_HI);
            const __nv_bfloat16* lb = (const __nv_bfloat16*)(smem + OX_LO);
            #pragma unroll 8
            for (int r = 0; r < 64; r++) {
                int row = half * 64 + r;
                float x = __bfloat162float(hb[row * LDB + col]) + __bfloat162float(lb[row * LDB + col]);
                s += x; q2 += x * x;
            }
            red[tid] = s; red[512 + tid] = q2;
            __syncthreads();
            if (tid < 256) {
                float ss = red[tid] + red[256 + tid];
                float qq = red[512 + tid] + red[768 + tid];
                float mu = ss * (1.0f / 128.0f);
                float var = qq * (1.0f / 128.0f) - mu * mu;
                muS[tid] = mu;
                rsS[tid] = rsqrtf(var + 1e-5f);
            }
        }

        #pragma unroll
        for (int s = 0; s < NSET; s++) {
            __syncthreads();
            const float* Wg = (s == 0) ? W0 : ((s == 1) ? W1 : W2);
            // stage W (LNIN: fold lnw)
            #pragma unroll
            for (int it = 0; it < 8; it++) {
                int idx = (it * 512 + tid) * 4;
                int co = idx >> 7, k = idx & 127;
                float4 v = *(const float4*)&Wg[(long)co * WROW + pass * 128 + k];
                if (LNIN) {
                    float4 wv = *(const float4*)&lnw[k];
                    v.x *= wv.x; v.y *= wv.y; v.z *= wv.z; v.w *= wv.w;
                }
                uint32_t h0, l0, h1, l1;
                split2(v.x, v.y, h0, l0);
                split2(v.z, v.w, h1, l1);
                uint32_t off = (uint32_t)(co * LDW + k) * 2;
                asm volatile("st.shared.v2.b32 [%0], {%1,%2};" :: "r"(sW_hi + off), "r"(h0), "r"(h1));
                asm volatile("st.shared.v2.b32 [%0], {%1,%2};" :: "r"(sW_lo + off), "r"(l0), "r"(l1));
            }
            if (LNIN) {
                // c1[co] = sum_k W[co,k]*lnb[k];  c2[co] = sum_k W[co,k]*lnw[k]
                int row = tid >> 2, part = tid & 3;
                float c1p = 0.f, c2p = 0.f;
                #pragma unroll
                for (int j = 0; j < 8; j++) {
                    int k = part * 32 + j * 4;
                    float4 wv = *(const float4*)&Wg[(long)row * WROW + k];
                    float4 lw = *(const float4*)&lnw[k];
                    float4 lbv = *(const float4*)&lnb[k];
                    c2p += wv.x*lw.x + wv.y*lw.y + wv.z*lw.z + wv.w*lw.w;
                    c1p += wv.x*lbv.x + wv.y*lbv.y + wv.z*lbv.z + wv.w*lbv.w;
                }
                c1p += __shfl_xor_sync(0xffffffffu, c1p, 1);
                c1p += __shfl_xor_sync(0xffffffffu, c1p, 2);
                c2p += __shfl_xor_sync(0xffffffffu, c2p, 1);
                c2p += __shfl_xor_sync(0xffffffffu, c2p, 2);
                if (part == 0) { c1S[row] = c1p; c2S[row] = c2p; }
            }
            __syncthreads();

            if (KPASS == 1) {
                #pragma unroll
                for (int mt = 0; mt < 4; mt++)
                    #pragma unroll
                    for (int nt = 0; nt < 4; nt++)
                        #pragma unroll
                        for (int e = 0; e < 4; e++) C[mt][nt][e] = 0.f;
            }

            // 3 split products
            #pragma unroll
            for (int s3 = 0; s3 < 3; s3++) {
                uint32_t aBase = (s3 == 2) ? sW_lo : sW_hi;
                uint32_t bBase = (s3 == 1) ? sX_lo : sX_hi;
                #pragma unroll
                for (int kk = 0; kk < 8; kk++) {
                    int k0 = kk * 16;
                    uint32_t af[4][4];
                    #pragma unroll
                    for (int mt = 0; mt < 4; mt++)
                        ldsm_x4(af[mt], aBase + offW + (uint32_t)(mt * 16 * LDW + k0) * 2);
                    uint32_t bf_[2][4];
                    #pragma unroll
                    for (int bt = 0; bt < 2; bt++)
                        ldsm_x4_t(bf_[bt], bBase + offX + (uint32_t)(k0 * LDB + bt * 16) * 2);
                    #pragma unroll
                    for (int mt = 0; mt < 4; mt++)
                        #pragma unroll
                        for (int nt = 0; nt < 4; nt++)
                            mma_bf16(C[mt][nt], af[mt], bf_[nt >> 1][(nt & 1) * 2], bf_[nt >> 1][(nt & 1) * 2 + 1]);
                }
            }

            if (KPASS == 1 && STORE) {
                float* Yb = ((s == 0) ? Y0 : ((s == 1) ? Y1 : Y2)) + (long)bi * ystride;
                const int g = lane >> 2, i2 = (lane & 3) * 2;
                #pragma unroll
                for (int mt = 0; mt < 4; mt++) {
                    int row0 = m0 + mt * 16 + g;
                    float c1a = LNIN ? c1S[row0] : 0.f, c2a = LNIN ? c2S[row0] : 0.f;
                    float c1b = LNIN ? c1S[row0 + 8] : 0.f, c2b = LNIN ? c2S[row0 + 8] : 0.f;
                    #pragma unroll
                    for (int nt = 0; nt < 4; nt++) {
                        int lp = n0 + nt * 8 + i2;
                        float2 o0 = make_float2(C[mt][nt][0], C[mt][nt][1]);
                        float2 o1 = make_float2(C[mt][nt][2], C[mt][nt][3]);
                        if (LNIN) {
                            float mA = muS[lp], rA = rsS[lp];
                            float mB = muS[lp+1], rB = rsS[lp+1];
                            o0.x = rA * (o0.x - mA * c2a) + c1a;
                            o0.y = rB * (o0.y - mB * c2a) + c1a;
                            o1.x = rA * (o1.x - mA * c2b) + c1b;
                            o1.y = rB * (o1.y - mB * c2b) + c1b;
                        }
                        if (GOUT) {
                            o0.x = gelu_f(o0.x); o0.y = gelu_f(o0.y);
                            o1.x = gelu_f(o1.x); o1.y = gelu_f(o1.y);
                        }
                        *(float2*)&Yb[(long)row0 * PP + p0 + lp]       = o0;
                        *(float2*)&Yb[(long)(row0 + 8) * PP + p0 + lp] = o1;
                    }
                }
            }
        }
    }

    if (POOL) {
        __syncthreads();
        float* ps = (float*)smem;       // [128][8]
        float* pm = ps + 1024;          // [128][8]
        const int g = lane >> 2;
        #pragma unroll
        for (int mt = 0; mt < 4; mt++) {
            float s0 = 0.f, s1 = 0.f, m0v = -INFINITY, m1v = -INFINITY;
            #pragma unroll
            for (int nt = 0; nt < 4; nt++) {
                s0 += C[mt][nt][0] + C[mt][nt][1];
                m0v = fmaxf(m0v, fmaxf(C[mt][nt][0], C[mt][nt][1]));
                s1 += C[mt][nt][2] + C[mt][nt][3];
                m1v = fmaxf(m1v, fmaxf(C[mt][nt][2], C[mt][nt][3]));
            }
            #pragma unroll
            for (int o = 1; o <= 2; o <<= 1) {
                s0 += __shfl_xor_sync(0xffffffffu, s0, o);
                s1 += __shfl_xor_sync(0xffffffffu, s1, o);
                m0v = fmaxf(m0v, __shfl_xor_sync(0xffffffffu, m0v, o));
                m1v = fmaxf(m1v, __shfl_xor_sync(0xffffffffu, m1v, o));
            }
            if ((lane & 3) == 0) {
                int r0 = m0 + mt * 16 + g;
                ps[r0 * 8 + wn] = s0;       pm[r0 * 8 + wn] = m0v;
                ps[(r0 + 8) * 8 + wn] = s1; pm[(r0 + 8) * 8 + wn] = m1v;
            }
        }
        __syncthreads();
        if (tid < 128) {
            float s = 0.f, m = -INFINITY;
            #pragma unroll
            for (int j = 0; j < 8; j++) {
                s += ps[tid * 8 + j];
                m = fmaxf(m, pm[tid * 8 + j]);
            }
            psum[((long)(bi * CC + tid)) * NBX2 + blockIdx.x] = s;
            pmax[((long)(bi * CC + tid)) * NBX2 + blockIdx.x] = m;
        }
    }
}

// ---------------- depthwise 3x3 pad 1, float4 + warp-shuffle halo ----------------
template<bool SQ>
__global__ void __launch_bounds__(256) dw4_kernel(const float* __restrict__ x,
                                                  const float* __restrict__ w,
                                                  float* __restrict__ y,
                                                  float* __restrict__ sqpart) {
    const unsigned FULL = 0xffffffffu;
    int gidx = blockIdx.x * 256 + threadIdx.x;
    int bc = blockIdx.y;
    int lane = threadIdx.x & 31;
    int p = gidx * 4;
    int yy = p / WIMG, xx = p % WIMG;
    const float* xp = x + (size_t)bc * PP;
    const float* wc = w + (bc % CC) * 9;
    float kw[3][3];
    #pragma unroll
    for (int i = 0; i < 9; i++) kw[i/3][i%3] = wc[i];

    float4 acc = make_float4(0.f, 0.f, 0.f, 0.f);
    #pragma unroll
    for (int ky = 0; ky < 3; ky++) {
        int sy = yy + ky - 1;
        bool ok = (unsigned)sy < HIMG;
        const float* row = xp + (ok ? sy * WIMG + xx : 0);
        float4 c = ok ? *(const float4*)row : make_float4(0.f, 0.f, 0.f, 0.f);
        float lf = __shfl_up_sync(FULL, c.w, 1);
        float rt = __shfl_down_sync(FULL, c.x, 1);
        if (xx == 0) lf = 0.f;
        else if (lane == 0) lf = ok ? row[-1] : 0.f;
        if (xx + 4 == WIMG) rt = 0.f;
        else if (lane == 31) rt = ok ? row[4] : 0.f;
        float k0 = kw[ky][0], k1 = kw[ky][1], k2 = kw[ky][2];
        acc.x += k0 * lf  + k1 * c.x + k2 * c.y;
        acc.y += k0 * c.x + k1 * c.y + k2 * c.z;
        acc.z += k0 * c.y + k1 * c.z + k2 * c.w;
        acc.w += k0 * c.z + k1 * c.w + k2 * rt;
    }
    *(float4*)&y[(size_t)bc * PP + p] = acc;

    if (SQ) {
        float s = acc.x*acc.x + acc.y*acc.y + acc.z*acc.z + acc.w*acc.w;
        __shared__ float red[256];
        red[threadIdx.x] = s; __syncthreads();
        for (int o = 128; o > 0; o >>= 1) {
            if (threadIdx.x < o) red[threadIdx.x] += red[threadIdx.x + o];
            __syncthreads();
        }
        if (threadIdx.x == 0) sqpart[bc * NDW + blockIdx.x] = red[0];
    }
}

// ---------------- reduce dw sumsq partials -> norms ----------------
__global__ void normred_kernel(const float* __restrict__ sq, const float* __restrict__ sk,
                               float* __restrict__ nq, float* __restrict__ nk) {
    int r = blockIdx.x * blockDim.x + threadIdx.x;
    if (r >= BB * CC) return;
    float s = 0.f, t = 0.f;
    #pragma unroll 4
    for (int i = 0; i < NDW; i++) { s += sq[r * NDW + i]; t += sk[r * NDW + i]; }
    nq[r] = fmaxf(sqrtf(s), 1e-12f);
    nk[r] = fmaxf(sqrtf(t), 1e-12f);
}

// ---------------- Gram partials via HMMA (bf16 split) ----------------
// part[bn][ch][i][j] = sum_{p in chunk} q[i,p] * k[j,p]
// CTA: (chunk, bn). 9 sub-tiles of 128 px, accumulators held in regs.
#define LDK 136
#define GT_BYTES (64*LDK*2)          // 17408
#define GR_SMEM (4*GT_BYTES)         // 69632
__global__ void __launch_bounds__(256, 1) gram_mma(const float* __restrict__ q,
                                                   const float* __restrict__ k,
                                                   float* __restrict__ part) {
    extern __shared__ __align__(16) char smem[];
    uint32_t sb = smem_u32(smem);
    uint32_t sQ_hi = sb, sQ_lo = sb + GT_BYTES;
    uint32_t sK_hi = sb + 2*GT_BYTES, sK_lo = sb + 3*GT_BYTES;

    const int tid = threadIdx.x;
    const int wid = tid >> 5, lane = tid & 31;
    const int ch = blockIdx.x, bn = blockIdx.y;
    const float* qb = q + (size_t)bn * HD * PP + ch * CPX2;
    const float* kb = k + (size_t)bn * HD * PP + ch * CPX2;

    const int wm = wid & 1, wn = wid >> 1;        // 2 x 4
    const int m0 = wm * 32, n0 = wn * 16;
    const int ar = (lane & 7) + ((lane >> 3) & 1) * 8;
    const int ac = ((lane >> 4) & 1) * 8;
    const uint32_t offA = (uint32_t)((m0 + ar) * LDK + ac) * 2;
    const uint32_t offB = (uint32_t)((n0 + ar) * LDK + ac) * 2;

    float C[2][2][4];
    #pragma unroll
    for (int mt = 0; mt < 2; mt++)
        #pragma unroll
        for (int nt = 0; nt < 2; nt++)
            #pragma unroll
            for (int e = 0; e < 4; e++) C[mt][nt][e] = 0.f;

    for (int t = 0; t < CPX2 / 128; t++) {
        if (t > 0) __syncthreads();
        // stage q, k sub-tiles [64ch][128px] split
        #pragma unroll
        for (int it = 0; it < 8; it++) {
            int idx = (it * 256 + tid) * 4;
            int r = idx >> 7, n = idx & 127;
            float4 v = *(const float4*)&qb[(size_t)r * PP + t * 128 + n];
            uint32_t h0, l0, h1, l1;
            split2(v.x, v.y, h0, l0); split2(v.z, v.w, h1, l1);
            uint32_t off = (uint32_t)(r * LDK + n) * 2;
            asm volatile("st.shared.v2.b32 [%0], {%1,%2};" :: "r"(sQ_hi + off), "r"(h0), "r"(h1));
            asm volatile("st.shared.v2.b32 [%0], {%1,%2};" :: "r"(sQ_lo + off), "r"(l0), "r"(l1));
        }
        #pragma unroll
        for (int it = 0; it < 8; it++) {
            int idx = (it * 256 + tid) * 4;
            int r = idx >> 7, n = idx & 127;
            float4 v = *(const float4*)&kb[(size_t)r * PP + t * 128 + n];
            uint32_t h0, l0, h1, l1;
            split2(v.x, v.y, h0, l0); split2(v.z, v.w, h1, l1);
            uint32_t off = (uint32_t)(r * LDK + n) * 2;
            asm volatile("st.shared.v2.b32 [%0], {%1,%2};" :: "r"(sK_hi + off), "r"(h0), "r"(h1));
            asm volatile("st.shared.v2.b32 [%0], {%1,%2};" :: "r"(sK_lo + off), "r"(l0), "r"(l1));
        }
        __syncthreads();

        #pragma unroll
        for (int s3 = 0; s3 < 3; s3++) {
            uint32_t aBase = (s3 == 2) ? sQ_lo : sQ_hi;
            uint32_t bBase = (s3 == 1) ? sK_lo : sK_hi;
            #pragma unroll
            for (int kk = 0; kk < 8; kk++) {
                int k0 = kk * 16;
                uint32_t af[2][4];
                #pragma unroll
                for (int mt = 0; mt < 2; mt++)
                    ldsm_x4(af[mt], aBase + offA + (uint32_t)(mt * 16 * LDK + k0) * 2);
                uint32_t bf_[4];
                ldsm_x4(bf_, bBase + offB + (uint32_t)k0 * 2);
                // b frags (non-trans on [n][k]): nt0 = {r0,r2}, nt1 = {r1,r3}
                #pragma unroll
                for (int mt = 0; mt < 2; mt++) {
                    mma_bf16(C[mt][0], af[mt], bf_[0], bf_[2]);
                    mma_bf16(C[mt][1], af[mt], bf_[1], bf_[3]);
                }
            }
        }
    }

    // write partials
    float* pb = part + (((size_t)bn * NCH2 + ch) * HD) * HD;
    const int g = lane >> 2, i2 = (lane & 3) * 2;
    #pragma unroll
    for (int mt = 0; mt < 2; mt++) {
        int i = m0 + mt * 16 + g;
        #pragma unroll
        for (int nt = 0; nt < 2; nt++) {
            int j = n0 + nt * 8 + i2;
            pb[i * HD + j]       = C[mt][nt][0];
            pb[i * HD + j + 1]   = C[mt][nt][1];
            pb[(i + 8) * HD + j]     = C[mt][nt][2];
            pb[(i + 8) * HD + j + 1] = C[mt][nt][3];
        }
    }
}

// ---------------- reduce + softmax ----------------
__global__ void attn_softmax(const float* __restrict__ part, const float* __restrict__ nq,
                             const float* __restrict__ nk, const float* __restrict__ scale,
                             float* __restrict__ attnw_out, float* __restrict__ a) {
    int bn = blockIdx.x;
    int n = bn % NH;
    int warp = threadIdx.x / 32, lane = threadIdx.x % 32;
    float sc = scale[n];
    for (int i = warp; i < HD; i += 8) {
        float v[2];
        #pragma unroll
        for (int h = 0; h < 2; h++) {
            int j = lane + 32 * h;
            float s = 0.f;
            for (int ch = 0; ch < NCH2; ch++)
                s += part[(((size_t)bn * NCH2 + ch) * HD + i) * HD + j];
            s = s * sc / (nq[bn*HD + i] * nk[bn*HD + j]);
            attnw_out[((size_t)bn * HD + i) * HD + j] = s;
            v[h] = s;
        }
        float m = fmaxf(v[0], v[1]);
        #pragma unroll
        for (int o = 16; o; o >>= 1) m = fmaxf(m, __shfl_xor_sync(0xffffffffu, m, o));
        float e0 = expf(v[0] - m), e1 = expf(v[1] - m);
        float s = e0 + e1;
        #pragma unroll
        for (int o = 16; o; o >>= 1) s += __shfl_xor_sync(0xffffffffu, s, o);
        float inv = 1.0f / s;
        a[((size_t)bn * HD + i) * HD + lane]      = e0 * inv;
        a[((size_t)bn * HD + i) * HD + lane + 32] = e1 * inv;
    }
}

// ---------------- fused a@v + channel-LN ----------------
#define AV_SMEM (8192*4 + 128*132*4 + (2*1024 + 256)*4)
__global__ void __launch_bounds__(256) avln_kernel(
    const float* __restrict__ a, const float* __restrict__ v,
    const float* __restrict__ lnw, const float* __restrict__ lnb,
    float* __restrict__ t)
{
    extern __shared__ __align__(16) float dsm[];
    float* As = dsm;                    // [2][64][64]
    float* Vs = As + 8192;              // [128][132]
    float* redS = Vs + 128*132;         // [8][128]
    float* redQ = redS + 1024;          // [8][128]
    float* muA  = redQ + 1024;          // [128]
    float* rsA  = muA + 128;            // [128]

    const int tid = threadIdx.x;
    const int bi = blockIdx.y;
    const int p0 = blockIdx.x * 128;

    const float* ab = a + (size_t)bi * 2 * 4096;
    #pragma unroll
    for (int it = 0; it < 8; it++) {
        int idx = (it * 256 + tid) * 4;
        *(float4*)&As[idx] = *(const float4*)&ab[idx];
    }
    const float* vb = v + (size_t)bi * CC * PP;
    #pragma unroll
    for (int it = 0; it < 16; it++) {
        int idx = it * 256 + tid;
        int row = idx >> 5, n4 = idx & 31;
        *(float4*)&Vs[row * 132 + n4 * 4] = *(const float4*)&vb[(size_t)row * PP + p0 + n4 * 4];
    }
    __syncthreads();

    const int px4 = tid & 31;
    const int cg = tid >> 5;
    const int h = cg >> 2;
    const int cbase = cg * 16;
    const float* Ah = As + h * 4096;

    float4 acc[16];
    #pragma unroll
    for (int cl = 0; cl < 16; cl++) acc[cl] = make_float4(0.f, 0.f, 0.f, 0.f);

    #pragma unroll
    for (int j4 = 0; j4 < 16; j4++) {
        float4 vv0 = *(float4*)&Vs[(h*64 + j4*4 + 0) * 132 + px4*4];
        float4 vv1 = *(float4*)&Vs[(h*64 + j4*4 + 1) * 132 + px4*4];
        float4 vv2 = *(float4*)&Vs[(h*64 + j4*4 + 2) * 132 + px4*4];
        float4 vv3 = *(float4*)&Vs[(h*64 + j4*4 + 3) * 132 + px4*4];
        #pragma unroll
        for (int cl = 0; cl < 16; cl++) {
            int i = (cbase + cl) & 63;
            float4 a4 = *(float4*)&Ah[i * 64 + j4 * 4];
            acc[cl].x += a4.x*vv0.x + a4.y*vv1.x + a4.z*vv2.x + a4.w*vv3.x;
            acc[cl].y += a4.x*vv0.y + a4.y*vv1.y + a4.z*vv2.y + a4.w*vv3.y;
            acc[cl].z += a4.x*vv0.z + a4.y*vv1.z + a4.z*vv2.z + a4.w*vv3.z;
            acc[cl].w += a4.x*vv0.w + a4.y*vv1.w + a4.z*vv2.w + a4.w*vv3.w;
        }
    }

    float4 s4 = make_float4(0.f,0.f,0.f,0.f), q4 = make_float4(0.f,0.f,0.f,0.f);
    #pragma unroll
    for (int cl = 0; cl < 16; cl++) {
        s4.x += acc[cl].x; s4.y += acc[cl].y; s4.z += acc[cl].z; s4.w += acc[cl].w;
        q4.x += acc[cl].x*acc[cl].x; q4.y += acc[cl].y*acc[cl].y;
        q4.z += acc[cl].z*acc[cl].z; q4.w += acc[cl].w*acc[cl].w;
    }
    *(float4*)&redS[cg * 128 + px4 * 4] = s4;
    *(float4*)&redQ[cg * 128 + px4 * 4] = q4;
    __syncthreads();
    if (tid < 128) {
        float s = 0.f, q2 = 0.f;
        #pragma unroll
        for (int g = 0; g < 8; g++) { s += redS[g * 128 + tid]; q2 += redQ[g * 128 + tid]; }
        float mu = s * (1.0f / 128.0f);
        float var = q2 * (1.0f / 128.0f) - mu * mu;
        muA[tid] = mu;
        rsA[tid] = rsqrtf(var + 1e-5f);
    }
    __syncthreads();

    float4 mu4 = *(float4*)&muA[px4 * 4];
    float4 rs4 = *(float4*)&rsA[px4 * 4];
    float* tb = t + (size_t)bi * CC * PP;
    #pragma unroll
    for (int cl = 0; cl < 16; cl++) {
        int c = cbase + cl;
        float w = __ldg(&lnw[c]), b = __ldg(&lnb[c]);
        float4 o;
        o.x = (acc[cl].x - mu4.x) * rs4.x * w + b;
        o.y = (acc[cl].y - mu4.y) * rs4.y * w + b;
        o.z = (acc[cl].z - mu4.z) * rs4.z * w + b;
        o.w = (acc[cl].w - mu4.w) * rs4.w * w + b;
        *(float4*)&tb[(size_t)c * PP + p0 + px4 * 4] = o;
    }
}

// ---------------- pool partial reduce + ChannelGate ----------------
__global__ void gate_pool_kernel(const float* __restrict__ psum, const float* __restrict__ pmax,
                                 const float* __restrict__ w1, const float* __restrict__ b1,
                                 const float* __restrict__ w2, const float* __restrict__ b2,
                                 float* __restrict__ out) {
    __shared__ float sa[CC], sm_[CC], ha[8], hm[8];
    int c = threadIdx.x;
    for (int b = 0; b < BB; b++) {
        float s = 0.f, m = -INFINITY;
        long base = (long)(b * CC + c) * NBX2;
        for (int i = 0; i < NBX2; i++) {
            s += psum[base + i];
            m = fmaxf(m, pmax[base + i]);
        }
        sa[c] = s * (1.0f / PP);
        sm_[c] = m;
        __syncthreads();
        if (c < 8) {
            float xa = b1[c], xm = b1[c];
            for (int cc = 0; cc < CC; cc++) {
                xa += w1[c*CC + cc] * sa[cc];
                xm += w1[c*CC + cc] * sm_[cc];
            }
            ha[c] = fmaxf(xa, 0.f);
            hm[c] = fmaxf(xm, 0.f);
        }
        __syncthreads();
        float xa = b2[c], xm = b2[c];
        #pragma unroll
        for (int j = 0; j < 8; j++) {
            xa += w2[c*8 + j] * ha[j];
            xm += w2[c*8 + j] * hm[j];
        }
        out[b*CC + c] = 1.0f / (1.0f + expf(-(xa + xm)));
        __syncthreads();
    }
}

// ---------------- host launch ----------------
static float* sym(const void* s) {
    void* p = nullptr;
    cudaGetSymbolAddress(&p, s);
    return (float*)p;
}

extern "C" void kernel_launch(void* const* d_in, const int* in_sizes, int n_in,
                              void* d_out, int out_size) {
    const float* x       = (const float*)d_in[0];
    const float* ln_in_w = (const float*)d_in[1];
    const float* ln_in_b = (const float*)d_in[2];
    const float* wq_pw   = (const float*)d_in[3];
    const float* wq_dw   = (const float*)d_in[4];
    const float* wk_pw   = (const float*)d_in[5];
    const float* wk_dw   = (const float*)d_in[6];
    const float* wv_pw   = (const float*)d_in[7];
    const float* wv_dw   = (const float*)d_in[8];
    const float* scale   = (const float*)d_in[9];
    const float* ln_o_w  = (const float*)d_in[10];
    const float* ln_o_b  = (const float*)d_in[11];
    const float* f1_pw   = (const float*)d_in[12];
    const float* f1_dw   = (const float*)d_in[13];
    const float* f2_pw   = (const float*)d_in[14];
    const float* f2_dw   = (const float*)d_in[15];
    const float* f_out   = (const float*)d_in[16];
    const float* g_w1    = (const float*)d_in[17];
    const float* g_b1    = (const float*)d_in[18];
    const float* g_w2    = (const float*)d_in[19];
    const float* g_b2    = (const float*)d_in[20];
    float* out = (float*)d_out;

    float* t  = sym(g_t);   float* t2 = sym(g_t2);  float* t3 = sym(g_t3);
    float* q  = sym(g_q);   float* k  = sym(g_k);   float* v  = sym(g_v);
    float* nq = sym(g_norm_q); float* nk = sym(g_norm_k);
    float* part = sym(g_part); float* a = sym(g_a);
    float* sqq = sym(g_sqq);   float* sqk = sym(g_sqk);
    float* psum = sym(g_psum); float* pmax = sym(g_pmax);

    auto qkv  = gemm512<1,3,true, false,false,false,true>;
    auto f1f2 = gemm512<1,2,false,false,true, false,true>;
    auto fout = gemm512<2,1,false,true, false,true, false>;
    cudaFuncSetAttribute(qkv,  cudaFuncAttributeMaxDynamicSharedMemorySize, SM512);
    cudaFuncSetAttribute(f1f2, cudaFuncAttributeMaxDynamicSharedMemorySize, SM512);
    cudaFuncSetAttribute(fout, cudaFuncAttributeMaxDynamicSharedMemorySize, SM512);
    cudaFuncSetAttribute(gram_mma, cudaFuncAttributeMaxDynamicSharedMemorySize, GR_SMEM);
    cudaFuncSetAttribute(avln_kernel, cudaFuncAttributeMaxDynamicSharedMemorySize, AV_SMEM);

    const long SB = (long)CC * PP;
    dim3 gGrid(NBX2, BB);
    dim3 dwGrid(NDW, BB*CC);
    dim3 avGrid(NBX, BB);

    // 1) fused LN + QKV pointwise (LN folded into W/epilogue)
    qkv<<<gGrid, 512, SM512>>>(wq_pw, wk_pw, wv_pw, x, nullptr, SB,
                               ln_in_w, ln_in_b, t, t2, t3, SB, nullptr, nullptr);
    // 2) depthwise (+ sumsq partials for q,k)
    dw4_kernel<true ><<<dwGrid, 256>>>(t,  wq_dw, q, sqq);
    dw4_kernel<true ><<<dwGrid, 256>>>(t2, wk_dw, k, sqk);
    dw4_kernel<false><<<dwGrid, 256>>>(t3, wv_dw, v, nullptr);
    // 3) norms
    normred_kernel<<<2, 256>>>(sqq, sqk, nq, nk);
    // 4) Gram (HMMA) + softmax (attn_weight -> d_out + 512)
    gram_mma<<<dim3(NCH2, BNH), 256, GR_SMEM>>>(q, k, part);
    attn_softmax<<<BNH, 256>>>(part, nq, nk, scale, out + BB*CC, a);
    // 5) fused a@v + LN -> t
    avln_kernel<<<avGrid, 256, AV_SMEM>>>(a, v, ln_o_w, ln_o_b, t);
    // 6) fused f1+f2 pointwise (GELU out) -> t2, t3
    f1f2<<<gGrid, 512, SM512>>>(f1_pw, f2_pw, nullptr, t, nullptr, SB,
                                nullptr, nullptr, t2, t3, nullptr, SB, nullptr, nullptr);
    // 7) depthwise FFN branches
    dw4_kernel<false><<<dwGrid, 256>>>(t2, f1_dw, q, nullptr);
    dw4_kernel<false><<<dwGrid, 256>>>(t3, f2_dw, k, nullptr);
    // 8) f_out (GELU in, K=256) -> pool partials only
    fout<<<gGrid, 512, SM512>>>(f_out, nullptr, nullptr, q, k, SB,
                                nullptr, nullptr, nullptr, nullptr, nullptr, SB, psum, pmax);
    // 9) ChannelGate
    gate_pool_kernel<<<1, 128>>>(psum, pmax, g_w1, g_b1, g_w2, g_b2, out);
}

// round 6
// speedup vs baseline: 1.2886x; 1.2886x over previous
#include <cuda_runtime.h>
#include <cuda_bf16.h>
#include <math.h>
#include <stdint.h>

// ---------------- problem constants ----------------
#define BB 4
#define CC 128
#define HIMG 192
#define WIMG 192
#define PP (HIMG*WIMG)          // 36864
#define NH 2
#define HD 64
#define BNH (BB*NH)             // 8
#define NBX (PP/128)            // 288
#define NDW 18                  // PP/2048 dw blocks per plane (8 px/thread)
#define NCH2 32                 // gram chunks per (b,head)
#define CPX2 (PP/NCH2)          // 1152

#define ELEMS ((size_t)BB*CC*PP)

// ---------------- scratch ----------------
__device__ float g_t [ELEMS];
__device__ float g_t2[ELEMS];
__device__ float g_t3[ELEMS];
__device__ float g_q [ELEMS];
__device__ float g_k [ELEMS];
__device__ float g_v [ELEMS];
__device__ float g_norm_q[BB*CC];
__device__ float g_norm_k[BB*CC];
__device__ float g_part[(size_t)BNH*NCH2*HD*HD];
__device__ float g_a[BNH*HD*HD];
__device__ float g_sqq[BB*CC*NDW];
__device__ float g_sqk[BB*CC*NDW];
__device__ float g_psum[BB*CC*NBX];
__device__ float g_pmax[BB*CC*NBX];

__device__ __forceinline__ float gelu_f(float x) {
    return 0.5f * x * (1.0f + erff(x * 0.70710678118654752f));
}

// ================= mma.sync helpers =================
__device__ __forceinline__ uint32_t smem_u32(const void* p) {
    uint32_t a;
    asm("{ .reg .u64 t; cvta.to.shared.u64 t, %1; cvt.u32.u64 %0, t; }" : "=r"(a) : "l"(p));
    return a;
}
__device__ __forceinline__ void ldsm_x4(uint32_t* r, uint32_t addr) {
    asm volatile("ldmatrix.sync.aligned.m8n8.x4.shared.b16 {%0,%1,%2,%3}, [%4];"
        : "=r"(r[0]), "=r"(r[1]), "=r"(r[2]), "=r"(r[3]) : "r"(addr));
}
__device__ __forceinline__ void ldsm_x4_t(uint32_t* r, uint32_t addr) {
    asm volatile("ldmatrix.sync.aligned.m8n8.x4.trans.shared.b16 {%0,%1,%2,%3}, [%4];"
        : "=r"(r[0]), "=r"(r[1]), "=r"(r[2]), "=r"(r[3]) : "r"(addr));
}
__device__ __forceinline__ void mma_bf16(float* c, const uint32_t* a, uint32_t b0, uint32_t b1) {
    asm volatile(
        "mma.sync.aligned.m16n8k16.row.col.f32.bf16.bf16.f32 "
        "{%0,%1,%2,%3}, {%4,%5,%6,%7}, {%8,%9}, {%0,%1,%2,%3};"
        : "+f"(c[0]), "+f"(c[1]), "+f"(c[2]), "+f"(c[3])
        : "r"(a[0]), "r"(a[1]), "r"(a[2]), "r"(a[3]), "r"(b0), "r"(b1));
}
__device__ __forceinline__ void split2(float x, float y, uint32_t& hi, uint32_t& lo) {
    __nv_bfloat16 hx = __float2bfloat16_rn(x);
    __nv_bfloat16 hy = __float2bfloat16_rn(y);
    __nv_bfloat16 lx = __float2bfloat16_rn(x - __bfloat162float(hx));
    __nv_bfloat16 ly = __float2bfloat16_rn(y - __bfloat162float(hy));
    hi = (uint32_t)__bfloat16_as_ushort(hx) | ((uint32_t)__bfloat16_as_ushort(hy) << 16);
    lo = (uint32_t)__bfloat16_as_ushort(lx) | ((uint32_t)__bfloat16_as_ushort(ly) << 16);
}

// ============== fused HMMA pointwise GEMM (R4-proven, 256 threads) ==============
#define LDA 136
#define TILE_BYTES (128*LDA*2)                  // 34816
#define MM_SMEM   (4*TILE_BYTES)                // 139264
#define XF_FLOATS (128*132)
#define MM_SMEM_LN (MM_SMEM + (XF_FLOATS + 768)*4)   // 209920

template<int KPASS, int NSET, bool LNIN, bool GIN, bool GOUT, bool POOL, bool STORE>
__global__ void __launch_bounds__(256, 1) gemm_fused(
    const float* __restrict__ W0, const float* __restrict__ W1, const float* __restrict__ W2,
    const float* __restrict__ X0, const float* __restrict__ X1, long xstride,
    const float* __restrict__ lnw, const float* __restrict__ lnb,
    float* __restrict__ Y0, float* __restrict__ Y1, float* __restrict__ Y2, long ystride,
    float* __restrict__ psum, float* __restrict__ pmax)
{
    extern __shared__ __align__(16) char smem[];
    uint32_t sX_hi = smem_u32(smem);
    uint32_t sX_lo = sX_hi + TILE_BYTES;
    uint32_t sW_hi = sX_lo + TILE_BYTES;
    uint32_t sW_lo = sW_hi + TILE_BYTES;
    float* Xf    = (float*)(smem + MM_SMEM);
    float* stats = Xf + XF_FLOATS;

    const int tid = threadIdx.x;
    const int wid = tid >> 5, lane = tid & 31;
    const int bi = blockIdx.y;
    const int p0 = blockIdx.x * 128;

    const int wm = wid & 1, wn = wid >> 1;
    const int m0 = wm * 64, n0 = wn * 32;
    const int ar = (lane & 7) + ((lane >> 3) & 1) * 8;
    const int ac = ((lane >> 4) & 1) * 8;
    const uint32_t offW = (uint32_t)((m0 + ar) * LDA + ac) * 2;
    const uint32_t offX = (uint32_t)(ar * LDA + n0 + ac) * 2;

    float C[4][4][4];
    if (KPASS > 1) {
        #pragma unroll
        for (int mt = 0; mt < 4; mt++)
            #pragma unroll
            for (int nt = 0; nt < 4; nt++)
                #pragma unroll
                for (int e = 0; e < 4; e++) C[mt][nt][e] = 0.f;
    }

    const int WROW = 128 * KPASS;

    #pragma unroll
    for (int pass = 0; pass < KPASS; pass++) {
        if (pass > 0) __syncthreads();
        const float* Xsrc = ((pass == 0) ? X0 : X1) + (long)bi * xstride;

        if (LNIN) {
            #pragma unroll
            for (int it = 0; it < 16; it++) {
                int idx = (it * 256 + tid) * 4;
                int kk = idx >> 7, nn = idx & 127;
                *(float4*)&Xf[kk * 132 + nn] = *(const float4*)&Xsrc[(long)kk * PP + p0 + nn];
            }
            __syncthreads();
            {
                int col = tid & 127, half = tid >> 7;
                float s = 0.f, q2 = 0.f;
                int r0 = half * 64;
                #pragma unroll 8
                for (int r = 0; r < 64; r++) {
                    float v = Xf[(r0 + r) * 132 + col];
                    s += v; q2 += v * v;
                }
                stats[half * 128 + col] = s;
                stats[256 + half * 128 + col] = q2;
            }
            __syncthreads();
            if (tid < 128) {
                float s = stats[tid] + stats[128 + tid];
                float q2 = stats[256 + tid] + stats[384 + tid];
                float mu = s * (1.0f / 128.0f);
                float var = q2 * (1.0f / 128.0f) - mu * mu;
                stats[512 + tid] = mu;
                stats[640 + tid] = rsqrtf(var + 1e-5f);
            }
            __syncthreads();
            #pragma unroll
            for (int it = 0; it < 16; it++) {
                int idx = (it * 256 + tid) * 4;
                int kk = idx >> 7, nn = idx & 127;
                float4 v = *(float4*)&Xf[kk * 132 + nn];
                float wc = __ldg(&lnw[kk]), bc = __ldg(&lnb[kk]);
                v.x = (v.x - stats[512 + nn + 0]) * stats[640 + nn + 0] * wc + bc;
                v.y = (v.y - stats[512 + nn + 1]) * stats[640 + nn + 1] * wc + bc;
                v.z = (v.z - stats[512 + nn + 2]) * stats[640 + nn + 2] * wc + bc;
                v.w = (v.w - stats[512 + nn + 3]) * stats[640 + nn + 3] * wc + bc;
                uint32_t h0, l0, h1, l1;
                split2(v.x, v.y, h0, l0);
                split2(v.z, v.w, h1, l1);
                uint32_t off = (uint32_t)(kk * LDA + nn) * 2;
                asm volatile("st.shared.v2.b32 [%0], {%1,%2};" :: "r"(sX_hi + off), "r"(h0), "r"(h1));
                asm volatile("st.shared.v2.b32 [%0], {%1,%2};" :: "r"(sX_lo + off), "r"(l0), "r"(l1));
            }
        } else {
            #pragma unroll
            for (int it = 0; it < 16; it++) {
                int idx = (it * 256 + tid) * 4;
                int kk = idx >> 7, nn = idx & 127;
                float4 v = *(const float4*)&Xsrc[(long)kk * PP + p0 + nn];
                if (GIN) { v.x = gelu_f(v.x); v.y = gelu_f(v.y); v.z = gelu_f(v.z); v.w = gelu_f(v.w); }
                uint32_t h0, l0, h1, l1;
                split2(v.x, v.y, h0, l0);
                split2(v.z, v.w, h1, l1);
                uint32_t off = (uint32_t)(kk * LDA + nn) * 2;
                asm volatile("st.shared.v2.b32 [%0], {%1,%2};" :: "r"(sX_hi + off), "r"(h0), "r"(h1));
                asm volatile("st.shared.v2.b32 [%0], {%1,%2};" :: "r"(sX_lo + off), "r"(l0), "r"(l1));
            }
        }

        #pragma unroll
        for (int s = 0; s < NSET; s++) {
            if (pass > 0 || s > 0) __syncthreads();
            const float* Wg = (s == 0) ? W0 : ((s == 1) ? W1 : W2);
            #pragma unroll
            for (int it = 0; it < 16; it++) {
                int idx = (it * 256 + tid) * 4;
                int co = idx >> 7, k = idx & 127;
                float4 v = *(const float4*)&Wg[(long)co * WROW + pass * 128 + k];
                uint32_t h0, l0, h1, l1;
                split2(v.x, v.y, h0, l0);
                split2(v.z, v.w, h1, l1);
                uint32_t off = (uint32_t)(co * LDA + k) * 2;
                asm volatile("st.shared.v2.b32 [%0], {%1,%2};" :: "r"(sW_hi + off), "r"(h0), "r"(h1));
                asm volatile("st.shared.v2.b32 [%0], {%1,%2};" :: "r"(sW_lo + off), "r"(l0), "r"(l1));
            }
            __syncthreads();

            if (KPASS == 1) {
                #pragma unroll
                for (int mt = 0; mt < 4; mt++)
                    #pragma unroll
                    for (int nt = 0; nt < 4; nt++)
                        #pragma unroll
                        for (int e = 0; e < 4; e++) C[mt][nt][e] = 0.f;
            }

            #pragma unroll
            for (int s3 = 0; s3 < 3; s3++) {
                uint32_t aBase = (s3 == 2) ? sW_lo : sW_hi;
                uint32_t bBase = (s3 == 1) ? sX_lo : sX_hi;
                #pragma unroll
                for (int kk = 0; kk < 8; kk++) {
                    int k0 = kk * 16;
                    uint32_t af[4][4];
                    #pragma unroll
                    for (int mt = 0; mt < 4; mt++)
                        ldsm_x4(af[mt], aBase + offW + (uint32_t)(mt * 16 * LDA + k0) * 2);
                    uint32_t bf_[2][4];
                    #pragma unroll
                    for (int bt = 0; bt < 2; bt++)
                        ldsm_x4_t(bf_[bt], bBase + offX + (uint32_t)(k0 * LDA + bt * 16) * 2);
                    #pragma unroll
                    for (int mt = 0; mt < 4; mt++)
                        #pragma unroll
                        for (int nt = 0; nt < 4; nt++)
                            mma_bf16(C[mt][nt], af[mt], bf_[nt >> 1][(nt & 1) * 2], bf_[nt >> 1][(nt & 1) * 2 + 1]);
                }
            }

            if (KPASS == 1 && STORE) {
                float* Yb = ((s == 0) ? Y0 : ((s == 1) ? Y1 : Y2)) + (long)bi * ystride;
                const int g = lane >> 2, i2 = (lane & 3) * 2;
                #pragma unroll
                for (int mt = 0; mt < 4; mt++) {
                    int row0 = m0 + mt * 16 + g;
                    #pragma unroll
                    for (int nt = 0; nt < 4; nt++) {
                        int p = p0 + n0 + nt * 8 + i2;
                        float2 o0 = make_float2(C[mt][nt][0], C[mt][nt][1]);
                        float2 o1 = make_float2(C[mt][nt][2], C[mt][nt][3]);
                        if (GOUT) {
                            o0.x = gelu_f(o0.x); o0.y = gelu_f(o0.y);
                            o1.x = gelu_f(o1.x); o1.y = gelu_f(o1.y);
                        }
                        *(float2*)&Yb[(long)row0 * PP + p]       = o0;
                        *(float2*)&Yb[(long)(row0 + 8) * PP + p] = o1;
                    }
                }
            }
        }
    }

    if (POOL) {
        __syncthreads();
        float* ps = (float*)smem;
        float* pm = ps + 512;
        const int g = lane >> 2;
        #pragma unroll
        for (int mt = 0; mt < 4; mt++) {
            float s0 = 0.f, s1 = 0.f, m0v = -INFINITY, m1v = -INFINITY;
            #pragma unroll
            for (int nt = 0; nt < 4; nt++) {
                s0 += C[mt][nt][0] + C[mt][nt][1];
                m0v = fmaxf(m0v, fmaxf(C[mt][nt][0], C[mt][nt][1]));
                s1 += C[mt][nt][2] + C[mt][nt][3];
                m1v = fmaxf(m1v, fmaxf(C[mt][nt][2], C[mt][nt][3]));
            }
            #pragma unroll
            for (int o = 1; o <= 2; o <<= 1) {
                s0 += __shfl_xor_sync(0xffffffffu, s0, o);
                s1 += __shfl_xor_sync(0xffffffffu, s1, o);
                m0v = fmaxf(m0v, __shfl_xor_sync(0xffffffffu, m0v, o));
                m1v = fmaxf(m1v, __shfl_xor_sync(0xffffffffu, m1v, o));
            }
            if ((lane & 3) == 0) {
                int r0 = m0 + mt * 16 + g;
                ps[r0 * 4 + wn] = s0;       pm[r0 * 4 + wn] = m0v;
                ps[(r0 + 8) * 4 + wn] = s1; pm[(r0 + 8) * 4 + wn] = m1v;
            }
        }
        __syncthreads();
        if (tid < 128) {
            float s = ps[tid*4] + ps[tid*4+1] + ps[tid*4+2] + ps[tid*4+3];
            float m = fmaxf(fmaxf(pm[tid*4], pm[tid*4+1]), fmaxf(pm[tid*4+2], pm[tid*4+3]));
            psum[((long)(bi * CC + tid)) * NBX + blockIdx.x] = s;
            pmax[((long)(bi * CC + tid)) * NBX + blockIdx.x] = m;
        }
    }
}

// ---------------- depthwise 3x3 pad 1: 2x4 px per thread, direct loads ----------------
template<bool SQ>
__global__ void __launch_bounds__(256) dw8_kernel(const float* __restrict__ x,
                                                  const float* __restrict__ w,
                                                  float* __restrict__ y,
                                                  float* __restrict__ sqpart) {
    int i = blockIdx.x * 256 + threadIdx.x;          // 0..4607 per plane
    int bc = blockIdx.y;
    int rp = i / 48, cg = i % 48;                    // 96 row-pairs, 48 col-groups
    int y0 = rp * 2, xx = cg * 4;
    const float* xp = x + (size_t)bc * PP;
    const float* wc = w + (bc % CC) * 9;
    float kw[3][3];
    #pragma unroll
    for (int j = 0; j < 9; j++) kw[j/3][j%3] = wc[j];

    float4 c[4]; float lf[4], rt[4];
    #pragma unroll
    for (int r = 0; r < 4; r++) {
        int sy = y0 - 1 + r;
        bool ok = (unsigned)sy < HIMG;
        const float* row = xp + sy * WIMG + xx;
        c[r]  = ok ? *(const float4*)row : make_float4(0.f, 0.f, 0.f, 0.f);
        lf[r] = (ok && xx > 0) ? row[-1] : 0.f;
        rt[r] = (ok && xx + 4 < WIMG) ? row[4] : 0.f;
    }

    float4 a0 = make_float4(0.f,0.f,0.f,0.f), a1 = make_float4(0.f,0.f,0.f,0.f);
    #pragma unroll
    for (int ky = 0; ky < 3; ky++) {
        float k0 = kw[ky][0], k1 = kw[ky][1], k2 = kw[ky][2];
        {   // output row y0 uses input rows r = ky
            float4 cc = c[ky]; float l = lf[ky], rr = rt[ky];
            a0.x += k0*l    + k1*cc.x + k2*cc.y;
            a0.y += k0*cc.x + k1*cc.y + k2*cc.z;
            a0.z += k0*cc.y + k1*cc.z + k2*cc.w;
            a0.w += k0*cc.z + k1*cc.w + k2*rr;
        }
        {   // output row y0+1 uses input rows r = ky+1
            float4 cc = c[ky+1]; float l = lf[ky+1], rr = rt[ky+1];
            a1.x += k0*l    + k1*cc.x + k2*cc.y;
            a1.y += k0*cc.x + k1*cc.y + k2*cc.z;
            a1.z += k0*cc.y + k1*cc.z + k2*cc.w;
            a1.w += k0*cc.z + k1*cc.w + k2*rr;
        }
    }
    float* yp = y + (size_t)bc * PP;
    *(float4*)&yp[y0 * WIMG + xx]       = a0;
    *(float4*)&yp[(y0 + 1) * WIMG + xx] = a1;

    if (SQ) {
        float s = a0.x*a0.x + a0.y*a0.y + a0.z*a0.z + a0.w*a0.w
                + a1.x*a1.x + a1.y*a1.y + a1.z*a1.z + a1.w*a1.w;
        __shared__ float red[256];
        red[threadIdx.x] = s; __syncthreads();
        for (int o = 128; o > 0; o >>= 1) {
            if (threadIdx.x < o) red[threadIdx.x] += red[threadIdx.x + o];
            __syncthreads();
        }
        if (threadIdx.x == 0) sqpart[bc * NDW + blockIdx.x] = red[0];
    }
}

// ---------------- reduce dw sumsq partials -> norms ----------------
__global__ void normred_kernel(const float* __restrict__ sq, const float* __restrict__ sk,
                               float* __restrict__ nq, float* __restrict__ nk) {
    int r = blockIdx.x * blockDim.x + threadIdx.x;
    if (r >= BB * CC) return;
    float s = 0.f, t = 0.f;
    #pragma unroll 6
    for (int i = 0; i < NDW; i++) { s += sq[r * NDW + i]; t += sk[r * NDW + i]; }
    nq[r] = fmaxf(sqrtf(s), 1e-12f);
    nk[r] = fmaxf(sqrtf(t), 1e-12f);
}

// ---------------- Gram partials via HMMA (bf16 split) — R5-proven ----------------
#define LDK 136
#define GT_BYTES (64*LDK*2)
#define GR_SMEM (4*GT_BYTES)
__global__ void __launch_bounds__(256, 1) gram_mma(const float* __restrict__ q,
                                                   const float* __restrict__ k,
                                                   float* __restrict__ part) {
    extern __shared__ __align__(16) char smem[];
    uint32_t sb = smem_u32(smem);
    uint32_t sQ_hi = sb, sQ_lo = sb + GT_BYTES;
    uint32_t sK_hi = sb + 2*GT_BYTES, sK_lo = sb + 3*GT_BYTES;

    const int tid = threadIdx.x;
    const int wid = tid >> 5, lane = tid & 31;
    const int ch = blockIdx.x, bn = blockIdx.y;
    const float* qb = q + (size_t)bn * HD * PP + ch * CPX2;
    const float* kb = k + (size_t)bn * HD * PP + ch * CPX2;

    const int wm = wid & 1, wn = wid >> 1;
    const int m0 = wm * 32, n0 = wn * 16;
    const int ar = (lane & 7) + ((lane >> 3) & 1) * 8;
    const int ac = ((lane >> 4) & 1) * 8;
    const uint32_t offA = (uint32_t)((m0 + ar) * LDK + ac) * 2;
    const uint32_t offB = (uint32_t)((n0 + ar) * LDK + ac) * 2;

    float C[2][2][4];
    #pragma unroll
    for (int mt = 0; mt < 2; mt++)
        #pragma unroll
        for (int nt = 0; nt < 2; nt++)
            #pragma unroll
            for (int e = 0; e < 4; e++) C[mt][nt][e] = 0.f;

    for (int t = 0; t < CPX2 / 128; t++) {
        if (t > 0) __syncthreads();
        #pragma unroll
        for (int it = 0; it < 8; it++) {
            int idx = (it * 256 + tid) * 4;
            int r = idx >> 7, n = idx & 127;
            float4 v = *(const float4*)&qb[(size_t)r * PP + t * 128 + n];
            uint32_t h0, l0, h1, l1;
            split2(v.x, v.y, h0, l0); split2(v.z, v.w, h1, l1);
            uint32_t off = (uint32_t)(r * LDK + n) * 2;
            asm volatile("st.shared.v2.b32 [%0], {%1,%2};" :: "r"(sQ_hi + off), "r"(h0), "r"(h1));
            asm volatile("st.shared.v2.b32 [%0], {%1,%2};" :: "r"(sQ_lo + off), "r"(l0), "r"(l1));
        }
        #pragma unroll
        for (int it = 0; it < 8; it++) {
            int idx = (it * 256 + tid) * 4;
            int r = idx >> 7, n = idx & 127;
            float4 v = *(const float4*)&kb[(size_t)r * PP + t * 128 + n];
            uint32_t h0, l0, h1, l1;
            split2(v.x, v.y, h0, l0); split2(v.z, v.w, h1, l1);
            uint32_t off = (uint32_t)(r * LDK + n) * 2;
            asm volatile("st.shared.v2.b32 [%0], {%1,%2};" :: "r"(sK_hi + off), "r"(h0), "r"(h1));
            asm volatile("st.shared.v2.b32 [%0], {%1,%2};" :: "r"(sK_lo + off), "r"(l0), "r"(l1));
        }
        __syncthreads();

        #pragma unroll
        for (int s3 = 0; s3 < 3; s3++) {
            uint32_t aBase = (s3 == 2) ? sQ_lo : sQ_hi;
            uint32_t bBase = (s3 == 1) ? sK_lo : sK_hi;
            #pragma unroll
            for (int kk = 0; kk < 8; kk++) {
                int k0 = kk * 16;
                uint32_t af[2][4];
                #pragma unroll
                for (int mt = 0; mt < 2; mt++)
                    ldsm_x4(af[mt], aBase + offA + (uint32_t)(mt * 16 * LDK + k0) * 2);
                uint32_t bf_[4];
                ldsm_x4(bf_, bBase + offB + (uint32_t)k0 * 2);
                #pragma unroll
                for (int mt = 0; mt < 2; mt++) {
                    mma_bf16(C[mt][0], af[mt], bf_[0], bf_[2]);
                    mma_bf16(C[mt][1], af[mt], bf_[1], bf_[3]);
                }
            }
        }
    }

    float* pb = part + (((size_t)bn * NCH2 + ch) * HD) * HD;
    const int g = lane >> 2, i2 = (lane & 3) * 2;
    #pragma unroll
    for (int mt = 0; mt < 2; mt++) {
        int i = m0 + mt * 16 + g;
        #pragma unroll
        for (int nt = 0; nt < 2; nt++) {
            int j = n0 + nt * 8 + i2;
            pb[i * HD + j]       = C[mt][nt][0];
            pb[i * HD + j + 1]   = C[mt][nt][1];
            pb[(i + 8) * HD + j]     = C[mt][nt][2];
            pb[(i + 8) * HD + j + 1] = C[mt][nt][3];
        }
    }
}

// ---------------- reduce + softmax ----------------
__global__ void attn_softmax(const float* __restrict__ part, const float* __restrict__ nq,
                             const float* __restrict__ nk, const float* __restrict__ scale,
                             float* __restrict__ attnw_out, float* __restrict__ a) {
    int bn = blockIdx.x;
    int n = bn % NH;
    int warp = threadIdx.x / 32, lane = threadIdx.x % 32;
    float sc = scale[n];
    for (int i = warp; i < HD; i += 8) {
        float v[2];
        #pragma unroll
        for (int h = 0; h < 2; h++) {
            int j = lane + 32 * h;
            float s = 0.f;
            for (int ch = 0; ch < NCH2; ch++)
                s += part[(((size_t)bn * NCH2 + ch) * HD + i) * HD + j];
            s = s * sc / (nq[bn*HD + i] * nk[bn*HD + j]);
            attnw_out[((size_t)bn * HD + i) * HD + j] = s;
            v[h] = s;
        }
        float m = fmaxf(v[0], v[1]);
        #pragma unroll
        for (int o = 16; o; o >>= 1) m = fmaxf(m, __shfl_xor_sync(0xffffffffu, m, o));
        float e0 = expf(v[0] - m), e1 = expf(v[1] - m);
        float s = e0 + e1;
        #pragma unroll
        for (int o = 16; o; o >>= 1) s += __shfl_xor_sync(0xffffffffu, s, o);
        float inv = 1.0f / s;
        a[((size_t)bn * HD + i) * HD + lane]      = e0 * inv;
        a[((size_t)bn * HD + i) * HD + lane + 32] = e1 * inv;
    }
}

// ---------------- fused a@v + channel-LN ----------------
#define AV_SMEM (8192*4 + 128*132*4 + (2*1024 + 256)*4)
__global__ void __launch_bounds__(256) avln_kernel(
    const float* __restrict__ a, const float* __restrict__ v,
    const float* __restrict__ lnw, const float* __restrict__ lnb,
    float* __restrict__ t)
{
    extern __shared__ __align__(16) float dsm[];
    float* As = dsm;
    float* Vs = As + 8192;
    float* redS = Vs + 128*132;
    float* redQ = redS + 1024;
    float* muA  = redQ + 1024;
    float* rsA  = muA + 128;

    const int tid = threadIdx.x;
    const int bi = blockIdx.y;
    const int p0 = blockIdx.x * 128;

    const float* ab = a + (size_t)bi * 2 * 4096;
    #pragma unroll
    for (int it = 0; it < 8; it++) {
        int idx = (it * 256 + tid) * 4;
        *(float4*)&As[idx] = *(const float4*)&ab[idx];
    }
    const float* vb = v + (size_t)bi * CC * PP;
    #pragma unroll
    for (int it = 0; it < 16; it++) {
        int idx = it * 256 + tid;
        int row = idx >> 5, n4 = idx & 31;
        *(float4*)&Vs[row * 132 + n4 * 4] = *(const float4*)&vb[(size_t)row * PP + p0 + n4 * 4];
    }
    __syncthreads();

    const int px4 = tid & 31;
    const int cg = tid >> 5;
    const int h = cg >> 2;
    const int cbase = cg * 16;
    const float* Ah = As + h * 4096;

    float4 acc[16];
    #pragma unroll
    for (int cl = 0; cl < 16; cl++) acc[cl] = make_float4(0.f, 0.f, 0.f, 0.f);

    #pragma unroll
    for (int j4 = 0; j4 < 16; j4++) {
        float4 vv0 = *(float4*)&Vs[(h*64 + j4*4 + 0) * 132 + px4*4];
        float4 vv1 = *(float4*)&Vs[(h*64 + j4*4 + 1) * 132 + px4*4];
        float4 vv2 = *(float4*)&Vs[(h*64 + j4*4 + 2) * 132 + px4*4];
        float4 vv3 = *(float4*)&Vs[(h*64 + j4*4 + 3) * 132 + px4*4];
        #pragma unroll
        for (int cl = 0; cl < 16; cl++) {
            int i = (cbase + cl) & 63;
            float4 a4 = *(float4*)&Ah[i * 64 + j4 * 4];
            acc[cl].x += a4.x*vv0.x + a4.y*vv1.x + a4.z*vv2.x + a4.w*vv3.x;
            acc[cl].y += a4.x*vv0.y + a4.y*vv1.y + a4.z*vv2.y + a4.w*vv3.y;
            acc[cl].z += a4.x*vv0.z + a4.y*vv1.z + a4.z*vv2.z + a4.w*vv3.z;
            acc[cl].w += a4.x*vv0.w + a4.y*vv1.w + a4.z*vv2.w + a4.w*vv3.w;
        }
    }

    float4 s4 = make_float4(0.f,0.f,0.f,0.f), q4 = make_float4(0.f,0.f,0.f,0.f);
    #pragma unroll
    for (int cl = 0; cl < 16; cl++) {
        s4.x += acc[cl].x; s4.y += acc[cl].y; s4.z += acc[cl].z; s4.w += acc[cl].w;
        q4.x += acc[cl].x*acc[cl].x; q4.y += acc[cl].y*acc[cl].y;
        q4.z += acc[cl].z*acc[cl].z; q4.w += acc[cl].w*acc[cl].w;
    }
    *(float4*)&redS[cg * 128 + px4 * 4] = s4;
    *(float4*)&redQ[cg * 128 + px4 * 4] = q4;
    __syncthreads();
    if (tid < 128) {
        float s = 0.f, q2 = 0.f;
        #pragma unroll
        for (int g = 0; g < 8; g++) { s += redS[g * 128 + tid]; q2 += redQ[g * 128 + tid]; }
        float mu = s * (1.0f / 128.0f);
        float var = q2 * (1.0f / 128.0f) - mu * mu;
        muA[tid] = mu;
        rsA[tid] = rsqrtf(var + 1e-5f);
    }
    __syncthreads();

    float4 mu4 = *(float4*)&muA[px4 * 4];
    float4 rs4 = *(float4*)&rsA[px4 * 4];
    float* tb = t + (size_t)bi * CC * PP;
    #pragma unroll
    for (int cl = 0; cl < 16; cl++) {
        int c = cbase + cl;
        float w = __ldg(&lnw[c]), b = __ldg(&lnb[c]);
        float4 o;
        o.x = (acc[cl].x - mu4.x) * rs4.x * w + b;
        o.y = (acc[cl].y - mu4.y) * rs4.y * w + b;
        o.z = (acc[cl].z - mu4.z) * rs4.z * w + b;
        o.w = (acc[cl].w - mu4.w) * rs4.w * w + b;
        *(float4*)&tb[(size_t)c * PP + p0 + px4 * 4] = o;
    }
}

// ---------------- pool partial reduce + ChannelGate ----------------
__global__ void gate_pool_kernel(const float* __restrict__ psum, const float* __restrict__ pmax,
                                 const float* __restrict__ w1, const float* __restrict__ b1,
                                 const float* __restrict__ w2, const float* __restrict__ b2,
                                 float* __restrict__ out) {
    __shared__ float sa[CC], sm_[CC], ha[8], hm[8];
    int c = threadIdx.x;
    for (int b = 0; b < BB; b++) {
        float s = 0.f, m = -INFINITY;
        long base = (long)(b * CC + c) * NBX;
        for (int i = 0; i < NBX; i++) {
            s += psum[base + i];
            m = fmaxf(m, pmax[base + i]);
        }
        sa[c] = s * (1.0f / PP);
        sm_[c] = m;
        __syncthreads();
        if (c < 8) {
            float xa = b1[c], xm = b1[c];
            for (int cc = 0; cc < CC; cc++) {
                xa += w1[c*CC + cc] * sa[cc];
                xm += w1[c*CC + cc] * sm_[cc];
            }
            ha[c] = fmaxf(xa, 0.f);
            hm[c] = fmaxf(xm, 0.f);
        }
        __syncthreads();
        float xa = b2[c], xm = b2[c];
        #pragma unroll
        for (int j = 0; j < 8; j++) {
            xa += w2[c*8 + j] * ha[j];
            xm += w2[c*8 + j] * hm[j];
        }
        out[b*CC + c] = 1.0f / (1.0f + expf(-(xa + xm)));
        __syncthreads();
    }
}

// ---------------- host launch ----------------
static float* sym(const void* s) {
    void* p = nullptr;
    cudaGetSymbolAddress(&p, s);
    return (float*)p;
}

extern "C" void kernel_launch(void* const* d_in, const int* in_sizes, int n_in,
                              void* d_out, int out_size) {
    const float* x       = (const float*)d_in[0];
    const float* ln_in_w = (const float*)d_in[1];
    const float* ln_in_b = (const float*)d_in[2];
    const float* wq_pw   = (const float*)d_in[3];
    const float* wq_dw   = (const float*)d_in[4];
    const float* wk_pw   = (const float*)d_in[5];
    const float* wk_dw   = (const float*)d_in[6];
    const float* wv_pw   = (const float*)d_in[7];
    const float* wv_dw   = (const float*)d_in[8];
    const float* scale   = (const float*)d_in[9];
    const float* ln_o_w  = (const float*)d_in[10];
    const float* ln_o_b  = (const float*)d_in[11];
    const float* f1_pw   = (const float*)d_in[12];
    const float* f1_dw   = (const float*)d_in[13];
    const float* f2_pw   = (const float*)d_in[14];
    const float* f2_dw   = (const float*)d_in[15];
    const float* f_out   = (const float*)d_in[16];
    const float* g_w1    = (const float*)d_in[17];
    const float* g_b1    = (const float*)d_in[18];
    const float* g_w2    = (const float*)d_in[19];
    const float* g_b2    = (const float*)d_in[20];
    float* out = (float*)d_out;

    float* t  = sym(g_t);   float* t2 = sym(g_t2);  float* t3 = sym(g_t3);
    float* q  = sym(g_q);   float* k  = sym(g_k);   float* v  = sym(g_v);
    float* nq = sym(g_norm_q); float* nk = sym(g_norm_k);
    float* part = sym(g_part); float* a = sym(g_a);
    float* sqq = sym(g_sqq);   float* sqk = sym(g_sqk);
    float* psum = sym(g_psum); float* pmax = sym(g_pmax);

    auto qkv  = gemm_fused<1,3,true, false,false,false,true>;
    auto f1f2 = gemm_fused<1,2,false,false,true, false,true>;
    auto fout = gemm_fused<2,1,false,true, false,true, false>;
    cudaFuncSetAttribute(qkv,  cudaFuncAttributeMaxDynamicSharedMemorySize, MM_SMEM_LN);
    cudaFuncSetAttribute(f1f2, cudaFuncAttributeMaxDynamicSharedMemorySize, MM_SMEM);
    cudaFuncSetAttribute(fout, cudaFuncAttributeMaxDynamicSharedMemorySize, MM_SMEM);
    cudaFuncSetAttribute(gram_mma, cudaFuncAttributeMaxDynamicSharedMemorySize, GR_SMEM);
    cudaFuncSetAttribute(avln_kernel, cudaFuncAttributeMaxDynamicSharedMemorySize, AV_SMEM);

    const long SB = (long)CC * PP;
    dim3 gGrid(NBX, BB);
    dim3 dwGrid(NDW, BB*CC);
    dim3 avGrid(NBX, BB);

    // 1) fused LN + QKV pointwise
    qkv<<<gGrid, 256, MM_SMEM_LN>>>(wq_pw, wk_pw, wv_pw, x, nullptr, SB,
                                    ln_in_w, ln_in_b, t, t2, t3, SB, nullptr, nullptr);
    // 2) depthwise (+ sumsq partials for q,k)
    dw8_kernel<true ><<<dwGrid, 256>>>(t,  wq_dw, q, sqq);
    dw8_kernel<true ><<<dwGrid, 256>>>(t2, wk_dw, k, sqk);
    dw8_kernel<false><<<dwGrid, 256>>>(t3, wv_dw, v, nullptr);
    // 3) norms
    normred_kernel<<<2, 256>>>(sqq, sqk, nq, nk);
    // 4) Gram (HMMA) + softmax (attn_weight -> d_out + 512)
    gram_mma<<<dim3(NCH2, BNH), 256, GR_SMEM>>>(q, k, part);
    attn_softmax<<<BNH, 256>>>(part, nq, nk, scale, out + BB*CC, a);
    // 5) fused a@v + LN -> t
    avln_kernel<<<avGrid, 256, AV_SMEM>>>(a, v, ln_o_w, ln_o_b, t);
    // 6) fused f1+f2 pointwise (GELU out) -> t2, t3
    f1f2<<<gGrid, 256, MM_SMEM>>>(f1_pw, f2_pw, nullptr, t, nullptr, SB,
                                  nullptr, nullptr, t2, t3, nullptr, SB, nullptr, nullptr);
    // 7) depthwise FFN branches
    dw8_kernel<false><<<dwGrid, 256>>>(t2, f1_dw, q, nullptr);
    dw8_kernel<false><<<dwGrid, 256>>>(t3, f2_dw, k, nullptr);
    // 8) f_out (GELU in, K=256) -> pool partials only
    fout<<<gGrid, 256, MM_SMEM>>>(f_out, nullptr, nullptr, q, k, SB,
                                  nullptr, nullptr, nullptr, nullptr, nullptr, SB, psum, pmax);
    // 9) ChannelGate
    gate_pool_kernel<<<1, 128>>>(psum, pmax, g_w1, g_b1, g_w2, g_b2, out);
}